// round 1
// baseline (speedup 1.0000x reference)
#include <cuda_runtime.h>
#include <cstdint>
#include <cstddef>

// ---------------------------------------------------------------------------
// SmallSpatialPolicyHead — restructured:
//   K_prep : repack weights (node-proj 48x160 k-major; trunk-proj 80x208 k-major)
//   K1     : trunk LN -> tproj(128) + h(80) (gfc1), per-block BN partial sums
//   K_bn   : finalize BN scale/shift
//   K2     : per-row fused: node LN -> 48x160 GEMM -> all heads (sett/city/road/robber)
//   K3     : BN + mish + gfc2 (only 122 needed output columns)
// ---------------------------------------------------------------------------

#define BMAX 16384
#define K1_GRID 296
#define K2_GRID 296
#define K3_GRID 592

__device__ float d_Wn[48 * 160];        // node projection, k-major [k][j]
__device__ float d_Wt[80 * 208];        // trunk projection, k-major [k][o]
__device__ float d_tb[208];             // combined first-layer biases
__device__ float d_tproj[(size_t)BMAX * 128];
__device__ float d_h[(size_t)BMAX * 80];
__device__ float d_partial[K1_GRID * 160];
__device__ float d_bnscale[80];
__device__ float d_bnshift[80];

__device__ __forceinline__ float mishf(float x) {
    float sp = (x > 20.f) ? x : log1pf(__expf(x));
    return x * tanhf(sp);
}

__device__ __forceinline__ float warp_sum(float v) {
    #pragma unroll
    for (int o = 16; o; o >>= 1) v += __shfl_xor_sync(0xffffffffu, v, o);
    return v;
}

// ------------------------------ prep ------------------------------
__global__ void k_prep(const float* __restrict__ sett1_w, const float* __restrict__ city1_w,
                       const float* __restrict__ road1_w, const float* __restrict__ rob1_w,
                       const float* __restrict__ gfc1_w,
                       const float* __restrict__ sett1_b, const float* __restrict__ city1_b,
                       const float* __restrict__ road1_b, const float* __restrict__ rob1_b,
                       const float* __restrict__ gfc1_b) {
    int i = blockIdx.x * blockDim.x + threadIdx.x;
    if (i < 48 * 160) {  // Wn[k][j]: j: 0:32 sett, 32:64 city, 64:96 road-src, 96:128 road-dst, 128:160 rob
        int k = i / 160, j = i % 160;
        float v;
        if (j < 32)       v = sett1_w[j * 128 + 80 + k];
        else if (j < 64)  v = city1_w[(j - 32) * 128 + 80 + k];
        else if (j < 96)  v = road1_w[(j - 64) * 176 + 80 + k];
        else if (j < 128) v = road1_w[(j - 96) * 176 + 128 + k];
        else              v = rob1_w[(j - 128) * 128 + 80 + k];
        d_Wn[i] = v;
    }
    if (i < 80 * 208) {  // Wt[k][o]: o: 0:32 sett, 32:64 city, 64:96 road, 96:128 rob, 128:208 gfc1
        int k = i / 208, o = i % 208;
        float v;
        if (o < 32)       v = sett1_w[o * 128 + k];
        else if (o < 64)  v = city1_w[(o - 32) * 128 + k];
        else if (o < 96)  v = road1_w[(o - 64) * 176 + k];
        else if (o < 128) v = rob1_w[(o - 96) * 128 + k];
        else              v = gfc1_w[(o - 128) * 80 + k];
        d_Wt[i] = v;
    }
    if (i < 208) {
        float v;
        if (i < 32)       v = sett1_b[i];
        else if (i < 64)  v = city1_b[i - 32];
        else if (i < 96)  v = road1_b[i - 64];
        else if (i < 128) v = rob1_b[i - 96];
        else              v = gfc1_b[i - 128];
        d_tb[i] = v;
    }
}

// ------------------------------ K1: trunk LN + projections ------------------------------
// 256 threads, warp-per-row. Lane j owns outputs o = j + 32c, c=0..6.
__global__ __launch_bounds__(256) void k1(const float* __restrict__ trunk,
                                          const float* __restrict__ ln_t_w,
                                          const float* __restrict__ ln_t_b, int B) {
    extern __shared__ float sm[];
    float* Wt_s = sm;              // 16640
    float* tb_s = Wt_s + 16640;    // 208
    float* lnw  = tb_s + 208;      // 80
    float* lnb  = lnw + 80;        // 80
    float* tn_s = lnb + 80;        // 8*80
    float* wred = tn_s + 640;      // 8*160

    int tid = threadIdx.x, wid = tid >> 5, lane = tid & 31;
    for (int i = tid; i < 16640; i += 256) Wt_s[i] = d_Wt[i];
    for (int i = tid; i < 208; i += 256) tb_s[i] = d_tb[i];
    if (tid < 80) { lnw[tid] = ln_t_w[tid]; lnb[tid] = ln_t_b[tid]; }
    __syncthreads();

    float s1[3] = {0.f, 0.f, 0.f}, s2[3] = {0.f, 0.f, 0.f};

    for (int b = blockIdx.x * 8 + wid; b < B; b += gridDim.x * 8) {
        const float* x = trunk + (size_t)b * 80;
        float x0 = x[lane], x1 = x[32 + lane];
        float x2 = (lane < 16) ? x[64 + lane] : 0.f;
        float s = warp_sum(x0 + x1 + x2);
        float q = warp_sum(x0 * x0 + x1 * x1 + x2 * x2);
        float mu = s * (1.f / 80.f);
        float is = rsqrtf(q * (1.f / 80.f) - mu * mu + 1e-5f);
        float* tn = tn_s + wid * 80;
        tn[lane]      = (x0 - mu) * is * lnw[lane] + lnb[lane];
        tn[32 + lane] = (x1 - mu) * is * lnw[32 + lane] + lnb[32 + lane];
        if (lane < 16) tn[64 + lane] = (x2 - mu) * is * lnw[64 + lane] + lnb[64 + lane];
        __syncwarp();

        float acc[7];
        #pragma unroll
        for (int c = 0; c < 7; c++) {
            int o = lane + 32 * c;
            acc[c] = (o < 208) ? tb_s[o] : 0.f;
        }
        for (int k = 0; k < 80; k++) {
            float v = tn[k];
            const float* wr = Wt_s + k * 208;
            #pragma unroll
            for (int c = 0; c < 7; c++) {
                int o = lane + 32 * c;
                if (o < 208) acc[c] += v * wr[o];
            }
        }
        __syncwarp();
        float* tp = d_tproj + (size_t)b * 128;
        #pragma unroll
        for (int c = 0; c < 4; c++) tp[lane + 32 * c] = acc[c];
        float* hp = d_h + (size_t)b * 80;
        hp[lane] = acc[4]; hp[32 + lane] = acc[5];
        s1[0] += acc[4]; s2[0] += acc[4] * acc[4];
        s1[1] += acc[5]; s2[1] += acc[5] * acc[5];
        if (lane < 16) {
            hp[64 + lane] = acc[6];
            s1[2] += acc[6]; s2[2] += acc[6] * acc[6];
        }
    }
    // deterministic per-warp partials -> block partial
    float* wr = wred + wid * 160;
    wr[lane] = s1[0]; wr[32 + lane] = s1[1];
    wr[80 + lane] = s2[0]; wr[112 + lane] = s2[1];
    if (lane < 16) { wr[64 + lane] = s1[2]; wr[144 + lane] = s2[2]; }
    __syncthreads();
    if (tid < 160) {
        float t = 0.f;
        #pragma unroll
        for (int w = 0; w < 8; w++) t += wred[w * 160 + tid];
        d_partial[blockIdx.x * 160 + tid] = t;
    }
}

// ------------------------------ BN finalize ------------------------------
__global__ void k_bn(const float* __restrict__ bn_w, const float* __restrict__ bn_b, int B) {
    int t = threadIdx.x;
    if (t >= 80) return;
    float S1 = 0.f, S2 = 0.f;
    for (int blk = 0; blk < K1_GRID; blk++) {
        S1 += d_partial[blk * 160 + t];
        S2 += d_partial[blk * 160 + 80 + t];
    }
    float invB = 1.f / (float)B;
    float mu = S1 * invB;
    float var = S2 * invB - mu * mu;
    float sc = bn_w[t] * rsqrtf(var + 1e-5f);
    d_bnscale[t] = sc;
    d_bnshift[t] = bn_b[t] - mu * sc;
}

// ------------------------------ K2: heavy fused per-row kernel ------------------------------
// 288 threads: 9 warps (LN: warp/node, heads: warp/task), GEMM: 18x16 tiles of 3n x 10j.
__global__ __launch_bounds__(288, 2) void k2(const float* __restrict__ node_emb,
                                             const float* __restrict__ ln_n_w,
                                             const float* __restrict__ ln_n_b,
                                             const int* __restrict__ road_pairs,
                                             const int* __restrict__ tile_nodes,
                                             const float* __restrict__ sett2_w, const float* __restrict__ sett2_b,
                                             const float* __restrict__ city2_w, const float* __restrict__ city2_b,
                                             const float* __restrict__ road2_w, const float* __restrict__ road2_b,
                                             const float* __restrict__ rob2_w, const float* __restrict__ rob2_b,
                                             float* __restrict__ out, int B) {
    extern __shared__ float sm[];
    float* Wn_s    = sm;                 // 7680
    float* xs      = Wn_s + 7680;        // 2592
    float* nn_s    = xs + 2592;          // 2592
    float* P_s     = nn_s + 2592;        // 8640
    float* tproj_s = P_s + 8640;         // 128
    float* w2_s    = tproj_s + 128;      // 96 (sett2, city2, road2)
    float* rob2_s  = w2_s + 96;          // 160
    float* b2_s    = rob2_s + 160;       // 8
    float* lnw     = b2_s + 8;           // 48
    float* lnb     = lnw + 48;           // 48
    float* out_s   = lnb + 48;           // 276
    int*   rp_s    = (int*)(out_s + 276);   // 144
    int*   ti_s    = rp_s + 144;             // 114

    int tid = threadIdx.x, wid = tid >> 5, lane = tid & 31;
    for (int i = tid; i < 7680; i += 288) Wn_s[i] = d_Wn[i];
    if (tid < 48) { lnw[tid] = ln_n_w[tid]; lnb[tid] = ln_n_b[tid]; }
    if (tid < 32) { w2_s[tid] = sett2_w[tid]; w2_s[32 + tid] = city2_w[tid]; w2_s[64 + tid] = road2_w[tid]; }
    if (tid < 160) rob2_s[tid] = rob2_w[tid];
    if (tid == 0) { b2_s[0] = sett2_b[0]; b2_s[1] = city2_b[0]; b2_s[2] = road2_b[0]; }
    if (tid < 5) b2_s[3 + tid] = rob2_b[tid];
    if (tid < 144) rp_s[tid] = road_pairs[tid];
    if (tid < 114) ti_s[tid] = tile_nodes[tid];
    __syncthreads();

    const int ntile = tid >> 4;       // 0..17
    const int ctile = tid & 15;       // 0..15
    const int n0 = ntile * 3;
    const int j0 = ctile * 10;

    for (int b = blockIdx.x; b < B; b += gridDim.x) {
        // stage raw node row + trunk projections
        const float* g = node_emb + (size_t)b * 2592;
        for (int i = tid; i < 2592; i += 288) xs[i] = g[i];
        if (tid < 128) tproj_s[tid] = d_tproj[(size_t)b * 128 + tid];
        __syncthreads();

        // LN per node (warp per node)
        for (int n = wid; n < 54; n += 9) {
            const float* xr = xs + n * 48;
            float x0 = xr[lane];
            float x1 = (lane < 16) ? xr[32 + lane] : 0.f;
            float s = warp_sum(x0 + x1);
            float q = warp_sum(x0 * x0 + x1 * x1);
            float mu = s * (1.f / 48.f);
            float is = rsqrtf(q * (1.f / 48.f) - mu * mu + 1e-5f);
            float* nr = nn_s + n * 48;
            nr[lane] = (x0 - mu) * is * lnw[lane] + lnb[lane];
            if (lane < 16) nr[32 + lane] = (x1 - mu) * is * lnw[32 + lane] + lnb[32 + lane];
        }
        __syncthreads();

        // GEMM: P[54][160] = nn[54][48] @ Wn[48][160]; 3n x 10j register tile
        {
            float acc[3][10];
            #pragma unroll
            for (int i = 0; i < 3; i++)
                #pragma unroll
                for (int j = 0; j < 10; j++) acc[i][j] = 0.f;
            const float* a0p = nn_s + n0 * 48;
            const float* a1p = a0p + 48;
            const float* a2p = a1p + 48;
            for (int k = 0; k < 48; k++) {
                float a0 = a0p[k], a1 = a1p[k], a2 = a2p[k];
                const float* wr = Wn_s + k * 160 + j0;
                #pragma unroll
                for (int j = 0; j < 10; j++) {
                    float w = wr[j];
                    acc[0][j] += a0 * w;
                    acc[1][j] += a1 * w;
                    acc[2][j] += a2 * w;
                }
            }
            #pragma unroll
            for (int i = 0; i < 3; i++) {
                float* pr = P_s + (n0 + i) * 160 + j0;
                #pragma unroll
                for (int j = 0; j < 10; j++) pr[j] = acc[i][j];
            }
        }
        __syncthreads();

        // heads: 199 warp tasks (54 sett, 54 city, 72 road, 19 robber)
        for (int task = wid; task < 199; task += 9) {
            if (task < 108) {
                int n = (task < 54) ? task : task - 54;
                int off = (task < 54) ? 0 : 32;
                float hv = tproj_s[off + lane] + P_s[n * 160 + off + lane];
                float r = warp_sum(mishf(hv) * w2_s[off + lane]);
                if (lane == 0) out_s[(task < 54) ? n : (54 + n)] = r + b2_s[(task < 54) ? 0 : 1];
            } else if (task < 180) {
                int e = task - 108;
                int sN = rp_s[2 * e], dN = rp_s[2 * e + 1];
                float hv = tproj_s[64 + lane] + P_s[sN * 160 + 64 + lane] + P_s[dN * 160 + 96 + lane];
                float r = warp_sum(mishf(hv) * w2_s[64 + lane]);
                if (lane == 0) out_s[108 + e] = r + b2_s[2];
            } else {
                int t = task - 180;
                float a = 0.f;
                #pragma unroll
                for (int i = 0; i < 6; i++) a += P_s[ti_s[t * 6 + i] * 160 + 128 + lane];
                float m = mishf(tproj_s[96 + lane] + a * (1.f / 6.f));
                #pragma unroll
                for (int i = 0; i < 5; i++) {
                    float r = warp_sum(m * rob2_s[i * 32 + lane]);
                    if (lane == 0) out_s[180 + t * 5 + i] = r + b2_s[3 + i];
                }
            }
        }
        __syncthreads();
        // out cols 5..279
        float* orow = out + (size_t)b * 397;
        for (int i = tid; i < 275; i += 288) orow[5 + i] = out_s[i];
        __syncthreads();
    }
}

// ------------------------------ K3: BN + mish + gfc2 (122 cols) ------------------------------
__global__ __launch_bounds__(128) void k3(const float* __restrict__ gfc2_w,
                                          const float* __restrict__ gfc2_b,
                                          float* __restrict__ out, int B) {
    __shared__ float Wg[80 * 122];
    __shared__ float bs[122];
    __shared__ float m_s[80];
    __shared__ float sc[80], sh[80];
    int tid = threadIdx.x;
    for (int i = tid; i < 80 * 122; i += 128) {
        int k = i / 122, t = i % 122;
        int r = (t < 5) ? t : (275 + t);
        Wg[i] = gfc2_w[r * 80 + k];
    }
    if (tid < 122) { int r = (tid < 5) ? tid : (275 + tid); bs[tid] = gfc2_b[r]; }
    if (tid < 80) { sc[tid] = d_bnscale[tid]; sh[tid] = d_bnshift[tid]; }
    __syncthreads();
    for (int b = blockIdx.x; b < B; b += gridDim.x) {
        if (tid < 80) m_s[tid] = mishf(d_h[(size_t)b * 80 + tid] * sc[tid] + sh[tid]);
        __syncthreads();
        if (tid < 122) {
            float a = bs[tid];
            for (int k = 0; k < 80; k++) a += m_s[k] * Wg[k * 122 + tid];
            int col = (tid < 5) ? tid : (275 + tid);
            out[(size_t)b * 397 + col] = a;
        }
        __syncthreads();
    }
}

// ------------------------------ launch ------------------------------
extern "C" void kernel_launch(void* const* d_in, const int* in_sizes, int n_in,
                              void* d_out, int out_size) {
    const float* trunk      = (const float*)d_in[0];
    const float* node_emb   = (const float*)d_in[1];
    const int*   road_pairs = (const int*)d_in[2];
    const int*   tile_nodes = (const int*)d_in[3];
    const float* ln_t_w = (const float*)d_in[4];
    const float* ln_t_b = (const float*)d_in[5];
    const float* ln_n_w = (const float*)d_in[6];
    const float* ln_n_b = (const float*)d_in[7];
    const float* gfc1_w = (const float*)d_in[8];
    const float* gfc1_b = (const float*)d_in[9];
    const float* bn_w   = (const float*)d_in[10];
    const float* bn_b   = (const float*)d_in[11];
    const float* gfc2_w = (const float*)d_in[12];
    const float* gfc2_b = (const float*)d_in[13];
    const float* sett1_w = (const float*)d_in[14];
    const float* sett1_b = (const float*)d_in[15];
    const float* sett2_w = (const float*)d_in[16];
    const float* sett2_b = (const float*)d_in[17];
    const float* city1_w = (const float*)d_in[18];
    const float* city1_b = (const float*)d_in[19];
    const float* city2_w = (const float*)d_in[20];
    const float* city2_b = (const float*)d_in[21];
    const float* road1_w = (const float*)d_in[22];
    const float* road1_b = (const float*)d_in[23];
    const float* road2_w = (const float*)d_in[24];
    const float* road2_b = (const float*)d_in[25];
    const float* rob1_w = (const float*)d_in[26];
    const float* rob1_b = (const float*)d_in[27];
    const float* rob2_w = (const float*)d_in[28];
    const float* rob2_b = (const float*)d_in[29];

    int B = in_sizes[0] / 80;
    if (B > BMAX) B = BMAX;
    float* out = (float*)d_out;

    const int K1_SMEM = (16640 + 208 + 80 + 80 + 640 + 1280) * 4;           // 75,712 B
    const int K2_SMEM = (7680 + 2592 + 2592 + 8640 + 128 + 96 + 160 + 8 +
                         48 + 48 + 276 + 144 + 114) * 4;                     // ~90,104 B

    cudaFuncSetAttribute(k1, cudaFuncAttributeMaxDynamicSharedMemorySize, K1_SMEM);
    cudaFuncSetAttribute(k2, cudaFuncAttributeMaxDynamicSharedMemorySize, K2_SMEM);

    k_prep<<<(80 * 208 + 255) / 256, 256>>>(sett1_w, city1_w, road1_w, rob1_w, gfc1_w,
                                            sett1_b, city1_b, road1_b, rob1_b, gfc1_b);
    k1<<<K1_GRID, 256, K1_SMEM>>>(trunk, ln_t_w, ln_t_b, B);
    k_bn<<<1, 80>>>(bn_w, bn_b, B);
    k2<<<K2_GRID, 288, K2_SMEM>>>(node_emb, ln_n_w, ln_n_b, road_pairs, tile_nodes,
                                  sett2_w, sett2_b, city2_w, city2_b,
                                  road2_w, road2_b, rob2_w, rob2_b, out, B);
    k3<<<K3_GRID, 128>>>(gfc2_w, gfc2_b, out, B);
}

// round 3
// speedup vs baseline: 1.4589x; 1.4589x over previous
#include <cuda_runtime.h>
#include <cuda_fp16.h>
#include <cstdint>
#include <cstddef>

// ---------------------------------------------------------------------------
// SmallSpatialPolicyHead — mma.sync (HMMA) version, baseline-PTX compatible.
//   k_prep : repack weights; split node-proj W into fp16 hi/lo [160][48]
//   k1     : trunk LN -> tproj(128) + h(80), BN partial sums
//   k_bn   : finalize BN scale/shift
//   k2     : per 2-batch-rows: node LN -> fp16 hi/lo split ->
//            mma.sync m16n8k16 (M=128,N=160,K=48, 3-term compensated),
//            register-resident epilogue -> all heads
//   k3     : BN + mish + gfc2 (122 needed cols)
// ---------------------------------------------------------------------------

#define BMAX 16384
#define K1_GRID 296
#define K2_GRID 148
#define K3_GRID 592

__device__ float d_Wt[80 * 208];
__device__ float d_tb[208];
__device__ __half d_Wh[160 * 48];
__device__ __half d_Wl[160 * 48];
__device__ float d_tproj[(size_t)BMAX * 128];
__device__ float d_h[(size_t)BMAX * 80];
__device__ float d_partial[K1_GRID * 160];
__device__ float d_bnscale[80];
__device__ float d_bnshift[80];

// ---- k2 smem byte offsets ----
#define SM_XS    0            // 5184 floats (20736 B)
#define SM_AH    20736        // 128x56 fp16 (14336 B)
#define SM_AL    35072        // 128x56 fp16
#define SM_WH    49408        // 160x56 fp16 (17920 B)
#define SM_WL    67328        // 160x56 fp16
#define SM_PS    85248        // 108x97 float (41904 B)
#define SM_TPROJ 127152       // 256 floats
#define SM_W2    128176       // 96 floats
#define SM_ROB2  128560       // 160 floats
#define SM_B2    129200       // 8 floats
#define SM_LNW   129232       // 48 floats
#define SM_LNB   129424       // 48 floats
#define SM_RP    129616       // 144 ints
#define SM_TI    130192       // 114 ints
#define SM_TOTAL 130656

__device__ __forceinline__ void mma16816(float* d, const uint32_t* a, uint32_t b0, uint32_t b1) {
    asm volatile(
        "mma.sync.aligned.m16n8k16.row.col.f32.f16.f16.f32 "
        "{%0,%1,%2,%3},{%4,%5,%6,%7},{%8,%9},{%0,%1,%2,%3};"
        : "+f"(d[0]), "+f"(d[1]), "+f"(d[2]), "+f"(d[3])
        : "r"(a[0]), "r"(a[1]), "r"(a[2]), "r"(a[3]), "r"(b0), "r"(b1));
}

__device__ __forceinline__ float mishf(float x) {
    float u = __expf(fminf(x, 15.f));
    float d = __fmaf_rn(u, u + 2.f, 2.f);
    return x - __fdividef(2.f * x, d);
}

__device__ __forceinline__ float warp_sum(float v) {
    #pragma unroll
    for (int o = 16; o; o >>= 1) v += __shfl_xor_sync(0xffffffffu, v, o);
    return v;
}

// ------------------------------ prep ------------------------------
__global__ void k_prep(const float* __restrict__ sett1_w, const float* __restrict__ city1_w,
                       const float* __restrict__ road1_w, const float* __restrict__ rob1_w,
                       const float* __restrict__ gfc1_w,
                       const float* __restrict__ sett1_b, const float* __restrict__ city1_b,
                       const float* __restrict__ road1_b, const float* __restrict__ rob1_b,
                       const float* __restrict__ gfc1_b) {
    int i = blockIdx.x * blockDim.x + threadIdx.x;
    if (i < 160 * 48) {  // node-proj W row j, col k; fp16 hi/lo split
        int j = i / 48, k = i % 48;
        float v;
        if (j < 32)       v = sett1_w[j * 128 + 80 + k];
        else if (j < 64)  v = city1_w[(j - 32) * 128 + 80 + k];
        else if (j < 96)  v = road1_w[(j - 64) * 176 + 80 + k];
        else if (j < 128) v = road1_w[(j - 96) * 176 + 128 + k];
        else              v = rob1_w[(j - 128) * 128 + 80 + k];
        __half h = __float2half(v);
        d_Wh[i] = h;
        d_Wl[i] = __float2half(v - __half2float(h));
    }
    if (i < 80 * 208) {
        int k = i / 208, o = i % 208;
        float v;
        if (o < 32)       v = sett1_w[o * 128 + k];
        else if (o < 64)  v = city1_w[(o - 32) * 128 + k];
        else if (o < 96)  v = road1_w[(o - 64) * 176 + k];
        else if (o < 128) v = rob1_w[(o - 96) * 128 + k];
        else              v = gfc1_w[(o - 128) * 80 + k];
        d_Wt[i] = v;
    }
    if (i < 208) {
        float v;
        if (i < 32)       v = sett1_b[i];
        else if (i < 64)  v = city1_b[i - 32];
        else if (i < 96)  v = road1_b[i - 64];
        else if (i < 128) v = rob1_b[i - 96];
        else              v = gfc1_b[i - 128];
        d_tb[i] = v;
    }
}

// ------------------------------ K1 ------------------------------
__global__ __launch_bounds__(256) void k1(const float* __restrict__ trunk,
                                          const float* __restrict__ ln_t_w,
                                          const float* __restrict__ ln_t_b, int B) {
    extern __shared__ float sm[];
    float* Wt_s = sm;
    float* tb_s = Wt_s + 16640;
    float* lnw  = tb_s + 208;
    float* lnb  = lnw + 80;
    float* tn_s = lnb + 80;
    float* wred = tn_s + 640;

    int tid = threadIdx.x, wid = tid >> 5, lane = tid & 31;
    for (int i = tid; i < 16640; i += 256) Wt_s[i] = d_Wt[i];
    for (int i = tid; i < 208; i += 256) tb_s[i] = d_tb[i];
    if (tid < 80) { lnw[tid] = ln_t_w[tid]; lnb[tid] = ln_t_b[tid]; }
    __syncthreads();

    float s1[3] = {0.f, 0.f, 0.f}, s2[3] = {0.f, 0.f, 0.f};

    for (int b = blockIdx.x * 8 + wid; b < B; b += gridDim.x * 8) {
        const float* x = trunk + (size_t)b * 80;
        float x0 = x[lane], x1 = x[32 + lane];
        float x2 = (lane < 16) ? x[64 + lane] : 0.f;
        float s = warp_sum(x0 + x1 + x2);
        float q = warp_sum(x0 * x0 + x1 * x1 + x2 * x2);
        float mu = s * (1.f / 80.f);
        float is = rsqrtf(q * (1.f / 80.f) - mu * mu + 1e-5f);
        float* tn = tn_s + wid * 80;
        tn[lane]      = (x0 - mu) * is * lnw[lane] + lnb[lane];
        tn[32 + lane] = (x1 - mu) * is * lnw[32 + lane] + lnb[32 + lane];
        if (lane < 16) tn[64 + lane] = (x2 - mu) * is * lnw[64 + lane] + lnb[64 + lane];
        __syncwarp();

        float acc[7];
        #pragma unroll
        for (int c = 0; c < 7; c++) {
            int o = lane + 32 * c;
            acc[c] = (o < 208) ? tb_s[o] : 0.f;
        }
        for (int k = 0; k < 80; k++) {
            float v = tn[k];
            const float* wr = Wt_s + k * 208;
            #pragma unroll
            for (int c = 0; c < 7; c++) {
                int o = lane + 32 * c;
                if (o < 208) acc[c] += v * wr[o];
            }
        }
        __syncwarp();
        float* tp = d_tproj + (size_t)b * 128;
        #pragma unroll
        for (int c = 0; c < 4; c++) tp[lane + 32 * c] = acc[c];
        float* hp = d_h + (size_t)b * 80;
        hp[lane] = acc[4]; hp[32 + lane] = acc[5];
        s1[0] += acc[4]; s2[0] += acc[4] * acc[4];
        s1[1] += acc[5]; s2[1] += acc[5] * acc[5];
        if (lane < 16) {
            hp[64 + lane] = acc[6];
            s1[2] += acc[6]; s2[2] += acc[6] * acc[6];
        }
    }
    float* wr = wred + wid * 160;
    wr[lane] = s1[0]; wr[32 + lane] = s1[1];
    wr[80 + lane] = s2[0]; wr[112 + lane] = s2[1];
    if (lane < 16) { wr[64 + lane] = s1[2]; wr[144 + lane] = s2[2]; }
    __syncthreads();
    if (tid < 160) {
        float t = 0.f;
        #pragma unroll
        for (int w = 0; w < 8; w++) t += wred[w * 160 + tid];
        d_partial[blockIdx.x * 160 + tid] = t;
    }
}

// ------------------------------ BN finalize ------------------------------
__global__ void k_bn(const float* __restrict__ bn_w, const float* __restrict__ bn_b, int B) {
    int t = threadIdx.x;
    if (t >= 80) return;
    float S1 = 0.f, S2 = 0.f;
    for (int blk = 0; blk < K1_GRID; blk++) {
        S1 += d_partial[blk * 160 + t];
        S2 += d_partial[blk * 160 + 80 + t];
    }
    float invB = 1.f / (float)B;
    float mu = S1 * invB;
    float var = S2 * invB - mu * mu;
    float sc = bn_w[t] * rsqrtf(var + 1e-5f);
    d_bnscale[t] = sc;
    d_bnshift[t] = bn_b[t] - mu * sc;
}

// ------------------------------ K2: HMMA fused kernel ------------------------------
__global__ __launch_bounds__(256, 1) void k2(const float* __restrict__ node_emb,
                                             const float* __restrict__ ln_n_w,
                                             const float* __restrict__ ln_n_b,
                                             const int* __restrict__ road_pairs,
                                             const int* __restrict__ tile_nodes,
                                             const float* __restrict__ sett2_w, const float* __restrict__ sett2_b,
                                             const float* __restrict__ city2_w, const float* __restrict__ city2_b,
                                             const float* __restrict__ road2_w, const float* __restrict__ road2_b,
                                             const float* __restrict__ rob2_w, const float* __restrict__ rob2_b,
                                             float* __restrict__ out, int B) {
    extern __shared__ char smem[];
    const int tid = threadIdx.x, wid = tid >> 5, lane = tid & 31;

    float* xs      = (float*)(smem + SM_XS);
    float* P_s     = (float*)(smem + SM_PS);
    float* tproj_s = (float*)(smem + SM_TPROJ);
    float* w2_s    = (float*)(smem + SM_W2);
    float* rob2_s  = (float*)(smem + SM_ROB2);
    float* b2_s    = (float*)(smem + SM_B2);
    float* lnw     = (float*)(smem + SM_LNW);
    float* lnb     = (float*)(smem + SM_LNB);
    int*   rp_s    = (int*)(smem + SM_RP);
    int*   ti_s    = (int*)(smem + SM_TI);

    // persistent loads: W hi/lo [160][56], head weights, LN params, indices
    for (int i = tid; i < 160 * 48; i += 256) {
        int n = i / 48, k = i % 48;
        *(__half*)(smem + SM_WH + (n * 56 + k) * 2) = d_Wh[i];
        *(__half*)(smem + SM_WL + (n * 56 + k) * 2) = d_Wl[i];
    }
    // zero A pad rows 108..127 (both buffers): 20*56 halfs = 560 u32 each
    for (int i = tid; i < 560; i += 256) {
        ((uint32_t*)(smem + SM_AH + 108 * 56 * 2))[i] = 0u;
        ((uint32_t*)(smem + SM_AL + 108 * 56 * 2))[i] = 0u;
    }
    if (tid < 48) { lnw[tid] = ln_n_w[tid]; lnb[tid] = ln_n_b[tid]; }
    if (tid < 32) { w2_s[tid] = sett2_w[tid]; w2_s[32 + tid] = city2_w[tid]; w2_s[64 + tid] = road2_w[tid]; }
    if (tid < 160) rob2_s[tid] = rob2_w[tid];
    if (tid == 0) { b2_s[0] = sett2_b[0]; b2_s[1] = city2_b[0]; b2_s[2] = road2_b[0]; }
    if (tid < 5) b2_s[3 + tid] = rob2_b[tid];
    if (tid < 144) rp_s[tid] = road_pairs[tid];
    if (tid < 114) ti_s[tid] = tile_nodes[tid];

    const int g = lane >> 2;             // 0..7
    const int k0 = (lane & 3) * 2;       // 0,2,4,6
    const int mrow = (wid & 3) * 32;     // m-pair base row
    const int nbase = (wid >> 2) * 10;   // n-tile range start

    // per-slot row info (loop invariant): slot = 2*t + h, row = mrow + 16t + 8h + g
    int rown[4]; const float* tpp[4];
    #pragma unroll
    for (int s = 0; s < 4; s++) {
        rown[s] = mrow + 16 * (s >> 1) + 8 * (s & 1) + g;
        tpp[s] = tproj_s + ((rown[s] >= 54) ? 128 : 0);
    }

    const long npairs = ((long)B + 1) / 2;
    const size_t tot4 = (size_t)B * 648;
    const size_t totp = (size_t)B * 128;
    const float4* ne4 = (const float4*)node_emb;

    float4 pf[6];
    float pft = 0.f;
    long pair = blockIdx.x;
    if (pair < npairs) {
        size_t b4 = (size_t)pair * 1296;
        #pragma unroll
        for (int q = 0; q < 6; q++) {
            size_t ix = b4 + tid + q * 256;
            pf[q] = (tid + q * 256 < 1296 && ix < tot4) ? ne4[ix] : make_float4(0.f, 0.f, 0.f, 0.f);
        }
        size_t tix = (size_t)pair * 256 + tid;
        pft = (tix < totp) ? d_tproj[tix] : 0.f;
    }

    for (; pair < npairs; pair += gridDim.x) {
        // stage xs + tproj
        #pragma unroll
        for (int q = 0; q < 6; q++) {
            int il = tid + q * 256;
            if (il < 1296) ((float4*)xs)[il] = pf[q];
        }
        tproj_s[tid] = pft;
        __syncthreads();

        // prefetch next
        long nxt = pair + gridDim.x;
        if (nxt < npairs) {
            size_t b4 = (size_t)nxt * 1296;
            #pragma unroll
            for (int q = 0; q < 6; q++) {
                size_t ix = b4 + tid + q * 256;
                pf[q] = (tid + q * 256 < 1296 && ix < tot4) ? ne4[ix] : make_float4(0.f, 0.f, 0.f, 0.f);
            }
            size_t tix = (size_t)nxt * 256 + tid;
            pft = (tix < totp) ? d_tproj[tix] : 0.f;
        }

        const int nrows = (int)((long)B * 54 - pair * 108 >= 108 ? 108 : (long)B * 54 - pair * 108);

        // LN + fp16 hi/lo split -> A buffers [row][56]
        for (int r = wid; r < nrows; r += 8) {
            const float* xr = xs + r * 48;
            float x0 = xr[lane];
            float x1 = (lane < 16) ? xr[32 + lane] : 0.f;
            float s = warp_sum(x0 + x1);
            float q = warp_sum(x0 * x0 + x1 * x1);
            float mu = s * (1.f / 48.f);
            float is = rsqrtf(q * (1.f / 48.f) - mu * mu + 1e-5f);
            float v0 = (x0 - mu) * is * lnw[lane] + lnb[lane];
            {
                __half h = __float2half(v0);
                *(__half*)(smem + SM_AH + (r * 56 + lane) * 2) = h;
                *(__half*)(smem + SM_AL + (r * 56 + lane) * 2) = __float2half(v0 - __half2float(h));
            }
            if (lane < 16) {
                float v1 = (x1 - mu) * is * lnw[32 + lane] + lnb[32 + lane];
                __half h = __float2half(v1);
                *(__half*)(smem + SM_AH + (r * 56 + 32 + lane) * 2) = h;
                *(__half*)(smem + SM_AL + (r * 56 + 32 + lane) * 2) = __float2half(v1 - __half2float(h));
            }
        }
        __syncthreads();

        // hoist A fragments: [m-tile][k-step][4], hi and lo
        uint32_t afh[2][3][4], afl[2][3][4];
        #pragma unroll
        for (int t = 0; t < 2; t++) {
            #pragma unroll
            for (int ks = 0; ks < 3; ks++) {
                const char* ba = smem + SM_AH + ((mrow + 16 * t + g) * 56 + k0 + 16 * ks) * 2;
                afh[t][ks][0] = *(const uint32_t*)(ba);
                afh[t][ks][1] = *(const uint32_t*)(ba + 896);        // +8 rows
                afh[t][ks][2] = *(const uint32_t*)(ba + 16);         // +8 k
                afh[t][ks][3] = *(const uint32_t*)(ba + 896 + 16);
                const char* bl = ba + (SM_AL - SM_AH);
                afl[t][ks][0] = *(const uint32_t*)(bl);
                afl[t][ks][1] = *(const uint32_t*)(bl + 896);
                afl[t][ks][2] = *(const uint32_t*)(bl + 16);
                afl[t][ks][3] = *(const uint32_t*)(bl + 896 + 16);
            }
        }

        float sacc[4] = {0.f, 0.f, 0.f, 0.f}, cacc[4] = {0.f, 0.f, 0.f, 0.f};

        #pragma unroll
        for (int ni = 0; ni < 10; ni++) {
            const int nt = nbase + ni;
            float acc[2][4] = {{0.f, 0.f, 0.f, 0.f}, {0.f, 0.f, 0.f, 0.f}};
            const char* wb = smem + SM_WH + ((nt * 8 + g) * 56 + k0) * 2;
            #pragma unroll
            for (int ks = 0; ks < 3; ks++) {
                uint32_t bh0 = *(const uint32_t*)(wb + 32 * ks);
                uint32_t bh1 = *(const uint32_t*)(wb + 32 * ks + 16);
                uint32_t bl0 = *(const uint32_t*)(wb + 32 * ks + (SM_WL - SM_WH));
                uint32_t bl1 = *(const uint32_t*)(wb + 32 * ks + 16 + (SM_WL - SM_WH));
                #pragma unroll
                for (int t = 0; t < 2; t++) {
                    mma16816(acc[t], afh[t][ks], bh0, bh1);   // Ah*Wh
                    mma16816(acc[t], afh[t][ks], bl0, bl1);   // Ah*Wl
                    mma16816(acc[t], afl[t][ks], bh0, bh1);   // Al*Wh
                }
            }
            const int col = nt * 8 + k0;
            if (nt < 8) {
                // sett (nt<4) / city (4..7): in-register mish-dot partials
                float w2a = w2_s[col], w2b = w2_s[col + 1];
                float* dst = (nt < 4) ? sacc : cacc;
                #pragma unroll
                for (int s = 0; s < 4; s++) {
                    float v0 = acc[s >> 1][2 * (s & 1)];
                    float v1 = acc[s >> 1][2 * (s & 1) + 1];
                    dst[s] += mishf(v0 + tpp[s][col]) * w2a + mishf(v1 + tpp[s][col + 1]) * w2b;
                }
            } else {
                // raw P cols 64:160 -> smem for road/robber gathers
                #pragma unroll
                for (int s = 0; s < 4; s++) {
                    int r = rown[s];
                    if (r < 108) {
                        float* pr = P_s + r * 97 + (col - 64);
                        pr[0] = acc[s >> 1][2 * (s & 1)];
                        pr[1] = acc[s >> 1][2 * (s & 1) + 1];
                    }
                }
            }
        }

        // sett/city finalize (warps 0-3 own all 20 sett+city col-tiles? no:
        // warps 0-3 cover n-tiles 0..9 which include all of cols 0:64)
        if (wid < 4) {
            #pragma unroll
            for (int s = 0; s < 4; s++) {
                sacc[s] += __shfl_xor_sync(0xffffffffu, sacc[s], 1);
                sacc[s] += __shfl_xor_sync(0xffffffffu, sacc[s], 2);
                cacc[s] += __shfl_xor_sync(0xffffffffu, cacc[s], 1);
                cacc[s] += __shfl_xor_sync(0xffffffffu, cacc[s], 2);
            }
            if ((lane & 3) == 0) {
                #pragma unroll
                for (int s = 0; s < 4; s++) {
                    int r = rown[s];
                    if (r < nrows) {
                        int bl = (r >= 54) ? 1 : 0;
                        int n = r - 54 * bl;
                        size_t ob = ((size_t)(pair * 2 + bl)) * 397;
                        out[ob + 5 + n]  = sacc[s] + b2_s[0];
                        out[ob + 59 + n] = cacc[s] + b2_s[1];
                    }
                }
            }
        }
        __syncthreads();

        const int nb = (nrows > 54) ? 2 : 1;
        // road heads: nb*72 warp tasks
        for (int t = wid; t < nb * 72; t += 8) {
            int bl = t / 72, e = t - 72 * bl;
            int sN = rp_s[2 * e], dN = rp_s[2 * e + 1];
            float hv = tproj_s[bl * 128 + 64 + lane]
                     + P_s[(bl * 54 + sN) * 97 + lane]
                     + P_s[(bl * 54 + dN) * 97 + 32 + lane];
            float red = warp_sum(mishf(hv) * w2_s[64 + lane]);
            if (lane == 0) out[((size_t)(pair * 2 + bl)) * 397 + 113 + e] = red + b2_s[2];
        }
        // robber heads: nb*19 warp tasks
        for (int t = wid; t < nb * 19; t += 8) {
            int bl = t / 19, tt = t - 19 * bl;
            float a = 0.f;
            #pragma unroll
            for (int i = 0; i < 6; i++)
                a += P_s[(bl * 54 + ti_s[tt * 6 + i]) * 97 + 64 + lane];
            float m = mishf(tproj_s[bl * 128 + 96 + lane] + a * (1.f / 6.f));
            #pragma unroll
            for (int o = 0; o < 5; o++) {
                float red = warp_sum(m * rob2_s[o * 32 + lane]);
                if (lane == 0)
                    out[((size_t)(pair * 2 + bl)) * 397 + 185 + tt * 5 + o] = red + b2_s[3 + o];
            }
        }
        __syncthreads();
    }
}

// ------------------------------ K3 ------------------------------
__global__ __launch_bounds__(128) void k3(const float* __restrict__ gfc2_w,
                                          const float* __restrict__ gfc2_b,
                                          float* __restrict__ out, int B) {
    __shared__ float Wg[80 * 122];
    __shared__ float bs[122];
    __shared__ float m_s[80];
    __shared__ float sc[80], sh[80];
    int tid = threadIdx.x;
    for (int i = tid; i < 80 * 122; i += 128) {
        int k = i / 122, t = i % 122;
        int r = (t < 5) ? t : (275 + t);
        Wg[i] = gfc2_w[r * 80 + k];
    }
    if (tid < 122) { int r = (tid < 5) ? tid : (275 + tid); bs[tid] = gfc2_b[r]; }
    if (tid < 80) { sc[tid] = d_bnscale[tid]; sh[tid] = d_bnshift[tid]; }
    __syncthreads();
    for (int b = blockIdx.x; b < B; b += gridDim.x) {
        if (tid < 80) m_s[tid] = mishf(d_h[(size_t)b * 80 + tid] * sc[tid] + sh[tid]);
        __syncthreads();
        if (tid < 122) {
            float a = bs[tid];
            for (int k = 0; k < 80; k++) a += m_s[k] * Wg[k * 122 + tid];
            int col = (tid < 5) ? tid : (275 + tid);
            out[(size_t)b * 397 + col] = a;
        }
        __syncthreads();
    }
}

// ------------------------------ launch ------------------------------
extern "C" void kernel_launch(void* const* d_in, const int* in_sizes, int n_in,
                              void* d_out, int out_size) {
    const float* trunk      = (const float*)d_in[0];
    const float* node_emb   = (const float*)d_in[1];
    const int*   road_pairs = (const int*)d_in[2];
    const int*   tile_nodes = (const int*)d_in[3];
    const float* ln_t_w = (const float*)d_in[4];
    const float* ln_t_b = (const float*)d_in[5];
    const float* ln_n_w = (const float*)d_in[6];
    const float* ln_n_b = (const float*)d_in[7];
    const float* gfc1_w = (const float*)d_in[8];
    const float* gfc1_b = (const float*)d_in[9];
    const float* bn_w   = (const float*)d_in[10];
    const float* bn_b   = (const float*)d_in[11];
    const float* gfc2_w = (const float*)d_in[12];
    const float* gfc2_b = (const float*)d_in[13];
    const float* sett1_w = (const float*)d_in[14];
    const float* sett1_b = (const float*)d_in[15];
    const float* sett2_w = (const float*)d_in[16];
    const float* sett2_b = (const float*)d_in[17];
    const float* city1_w = (const float*)d_in[18];
    const float* city1_b = (const float*)d_in[19];
    const float* city2_w = (const float*)d_in[20];
    const float* city2_b = (const float*)d_in[21];
    const float* road1_w = (const float*)d_in[22];
    const float* road1_b = (const float*)d_in[23];
    const float* road2_w = (const float*)d_in[24];
    const float* road2_b = (const float*)d_in[25];
    const float* rob1_w = (const float*)d_in[26];
    const float* rob1_b = (const float*)d_in[27];
    const float* rob2_w = (const float*)d_in[28];
    const float* rob2_b = (const float*)d_in[29];

    int B = in_sizes[0] / 80;
    if (B > BMAX) B = BMAX;
    float* out = (float*)d_out;

    const int K1_SMEM = (16640 + 208 + 80 + 80 + 640 + 1280) * 4;

    cudaFuncSetAttribute(k1, cudaFuncAttributeMaxDynamicSharedMemorySize, K1_SMEM);
    cudaFuncSetAttribute(k2, cudaFuncAttributeMaxDynamicSharedMemorySize, SM_TOTAL);

    k_prep<<<(80 * 208 + 255) / 256, 256>>>(sett1_w, city1_w, road1_w, rob1_w, gfc1_w,
                                            sett1_b, city1_b, road1_b, rob1_b, gfc1_b);
    k1<<<K1_GRID, 256, K1_SMEM>>>(trunk, ln_t_w, ln_t_b, B);
    k_bn<<<1, 80>>>(bn_w, bn_b, B);
    k2<<<K2_GRID, 256, SM_TOTAL>>>(node_emb, ln_n_w, ln_n_b, road_pairs, tile_nodes,
                                   sett2_w, sett2_b, city2_w, city2_b,
                                   road2_w, road2_b, rob2_w, rob2_b, out, B);
    k3<<<K3_GRID, 128>>>(gfc2_w, gfc2_b, out, B);
}

// round 4
// speedup vs baseline: 2.2629x; 1.5511x over previous
#include <cuda_runtime.h>
#include <cuda_fp16.h>
#include <cstdint>
#include <cstddef>

// ---------------------------------------------------------------------------
// SmallSpatialPolicyHead — HMMA version, 2 CTAs/SM, cp.async staging,
// thread-per-row LN. xs/P_s smem overlay.
// ---------------------------------------------------------------------------

#define BMAX 16384
#define K1_GRID 296
#define K2_GRID 296
#define K3_GRID 592

__device__ float d_Wt[80 * 208];
__device__ float d_tb[208];
__device__ __half d_Wh[160 * 48];
__device__ __half d_Wl[160 * 48];
__device__ float d_tproj[(size_t)BMAX * 128];
__device__ float d_h[(size_t)BMAX * 80];
__device__ float d_partial[K1_GRID * 160];
__device__ float d_bnscale[80];
__device__ float d_bnshift[80];

// ---- k2 smem byte offsets ----
// xs: 108 rows x 52 floats (22464 B)  OVERLAID WITH  P_s: 108 x 97 floats (41904 B)
#define SM_XP    0
#define SM_AH    41904         // 128x56 fp16 = 14336
#define SM_AL    56240
#define SM_WH    70576         // 160x56 fp16 = 17920
#define SM_WL    88496
#define SM_TPROJ 106416        // 256 f
#define SM_W2    107440        // 96 f
#define SM_ROB2  107824        // 160 f
#define SM_B2    108464        // 8 f
#define SM_LNW   108496        // 48 f
#define SM_LNB   108688        // 48 f
#define SM_MU    108880        // 108 f
#define SM_IS    109312        // 108 f
#define SM_RP    109744        // 144 i
#define SM_TI    110320        // 114 i
#define SM_TOTAL 110776

__device__ __forceinline__ uint32_t smem_u32(const void* p) {
    uint32_t a;
    asm("{ .reg .u64 t; cvta.to.shared.u64 t, %1; cvt.u32.u64 %0, t; }" : "=r"(a) : "l"(p));
    return a;
}

__device__ __forceinline__ void cp16(uint32_t dst, const void* src) {
    asm volatile("cp.async.cg.shared.global [%0], [%1], 16;" :: "r"(dst), "l"(src));
}

__device__ __forceinline__ void mma16816(float* d, const uint32_t* a, uint32_t b0, uint32_t b1) {
    asm volatile(
        "mma.sync.aligned.m16n8k16.row.col.f32.f16.f16.f32 "
        "{%0,%1,%2,%3},{%4,%5,%6,%7},{%8,%9},{%0,%1,%2,%3};"
        : "+f"(d[0]), "+f"(d[1]), "+f"(d[2]), "+f"(d[3])
        : "r"(a[0]), "r"(a[1]), "r"(a[2]), "r"(a[3]), "r"(b0), "r"(b1));
}

__device__ __forceinline__ float mishf(float x) {
    float u = __expf(fminf(x, 15.f));
    float d = __fmaf_rn(u, u + 2.f, 2.f);
    return x - __fdividef(2.f * x, d);
}

__device__ __forceinline__ float warp_sum(float v) {
    #pragma unroll
    for (int o = 16; o; o >>= 1) v += __shfl_xor_sync(0xffffffffu, v, o);
    return v;
}

// ------------------------------ prep ------------------------------
__global__ void k_prep(const float* __restrict__ sett1_w, const float* __restrict__ city1_w,
                       const float* __restrict__ road1_w, const float* __restrict__ rob1_w,
                       const float* __restrict__ gfc1_w,
                       const float* __restrict__ sett1_b, const float* __restrict__ city1_b,
                       const float* __restrict__ road1_b, const float* __restrict__ rob1_b,
                       const float* __restrict__ gfc1_b) {
    int i = blockIdx.x * blockDim.x + threadIdx.x;
    if (i < 160 * 48) {
        int j = i / 48, k = i % 48;
        float v;
        if (j < 32)       v = sett1_w[j * 128 + 80 + k];
        else if (j < 64)  v = city1_w[(j - 32) * 128 + 80 + k];
        else if (j < 96)  v = road1_w[(j - 64) * 176 + 80 + k];
        else if (j < 128) v = road1_w[(j - 96) * 176 + 128 + k];
        else              v = rob1_w[(j - 128) * 128 + 80 + k];
        __half h = __float2half(v);
        d_Wh[i] = h;
        d_Wl[i] = __float2half(v - __half2float(h));
    }
    if (i < 80 * 208) {
        int k = i / 208, o = i % 208;
        float v;
        if (o < 32)       v = sett1_w[o * 128 + k];
        else if (o < 64)  v = city1_w[(o - 32) * 128 + k];
        else if (o < 96)  v = road1_w[(o - 64) * 176 + k];
        else if (o < 128) v = rob1_w[(o - 96) * 128 + k];
        else              v = gfc1_w[(o - 128) * 80 + k];
        d_Wt[i] = v;
    }
    if (i < 208) {
        float v;
        if (i < 32)       v = sett1_b[i];
        else if (i < 64)  v = city1_b[i - 32];
        else if (i < 96)  v = road1_b[i - 64];
        else if (i < 128) v = rob1_b[i - 96];
        else              v = gfc1_b[i - 128];
        d_tb[i] = v;
    }
}

// ------------------------------ K1 ------------------------------
__global__ __launch_bounds__(256) void k1(const float* __restrict__ trunk,
                                          const float* __restrict__ ln_t_w,
                                          const float* __restrict__ ln_t_b, int B) {
    extern __shared__ float sm[];
    float* Wt_s = sm;
    float* tb_s = Wt_s + 16640;
    float* lnw  = tb_s + 208;
    float* lnb  = lnw + 80;
    float* tn_s = lnb + 80;
    float* wred = tn_s + 640;

    int tid = threadIdx.x, wid = tid >> 5, lane = tid & 31;
    for (int i = tid; i < 16640; i += 256) Wt_s[i] = d_Wt[i];
    for (int i = tid; i < 208; i += 256) tb_s[i] = d_tb[i];
    if (tid < 80) { lnw[tid] = ln_t_w[tid]; lnb[tid] = ln_t_b[tid]; }
    __syncthreads();

    float s1[3] = {0.f, 0.f, 0.f}, s2[3] = {0.f, 0.f, 0.f};

    for (int b = blockIdx.x * 8 + wid; b < B; b += gridDim.x * 8) {
        const float* x = trunk + (size_t)b * 80;
        float x0 = x[lane], x1 = x[32 + lane];
        float x2 = (lane < 16) ? x[64 + lane] : 0.f;
        float s = warp_sum(x0 + x1 + x2);
        float q = warp_sum(x0 * x0 + x1 * x1 + x2 * x2);
        float mu = s * (1.f / 80.f);
        float is = rsqrtf(q * (1.f / 80.f) - mu * mu + 1e-5f);
        float* tn = tn_s + wid * 80;
        tn[lane]      = (x0 - mu) * is * lnw[lane] + lnb[lane];
        tn[32 + lane] = (x1 - mu) * is * lnw[32 + lane] + lnb[32 + lane];
        if (lane < 16) tn[64 + lane] = (x2 - mu) * is * lnw[64 + lane] + lnb[64 + lane];
        __syncwarp();

        float acc[7];
        #pragma unroll
        for (int c = 0; c < 7; c++) {
            int o = lane + 32 * c;
            acc[c] = (o < 208) ? tb_s[o] : 0.f;
        }
        for (int k = 0; k < 80; k++) {
            float v = tn[k];
            const float* wr = Wt_s + k * 208;
            #pragma unroll
            for (int c = 0; c < 7; c++) {
                int o = lane + 32 * c;
                if (o < 208) acc[c] += v * wr[o];
            }
        }
        __syncwarp();
        float* tp = d_tproj + (size_t)b * 128;
        #pragma unroll
        for (int c = 0; c < 4; c++) tp[lane + 32 * c] = acc[c];
        float* hp = d_h + (size_t)b * 80;
        hp[lane] = acc[4]; hp[32 + lane] = acc[5];
        s1[0] += acc[4]; s2[0] += acc[4] * acc[4];
        s1[1] += acc[5]; s2[1] += acc[5] * acc[5];
        if (lane < 16) {
            hp[64 + lane] = acc[6];
            s1[2] += acc[6]; s2[2] += acc[6] * acc[6];
        }
    }
    float* wr = wred + wid * 160;
    wr[lane] = s1[0]; wr[32 + lane] = s1[1];
    wr[80 + lane] = s2[0]; wr[112 + lane] = s2[1];
    if (lane < 16) { wr[64 + lane] = s1[2]; wr[144 + lane] = s2[2]; }
    __syncthreads();
    if (tid < 160) {
        float t = 0.f;
        #pragma unroll
        for (int w = 0; w < 8; w++) t += wred[w * 160 + tid];
        d_partial[blockIdx.x * 160 + tid] = t;
    }
}

// ------------------------------ BN finalize ------------------------------
__global__ void k_bn(const float* __restrict__ bn_w, const float* __restrict__ bn_b, int B) {
    int t = threadIdx.x;
    if (t >= 80) return;
    float S1 = 0.f, S2 = 0.f;
    for (int blk = 0; blk < K1_GRID; blk++) {
        S1 += d_partial[blk * 160 + t];
        S2 += d_partial[blk * 160 + 80 + t];
    }
    float invB = 1.f / (float)B;
    float mu = S1 * invB;
    float var = S2 * invB - mu * mu;
    float sc = bn_w[t] * rsqrtf(var + 1e-5f);
    d_bnscale[t] = sc;
    d_bnshift[t] = bn_b[t] - mu * sc;
}

// ------------------------------ K2: HMMA fused kernel ------------------------------
__global__ __launch_bounds__(256, 2) void k2(const float* __restrict__ node_emb,
                                             const float* __restrict__ ln_n_w,
                                             const float* __restrict__ ln_n_b,
                                             const int* __restrict__ road_pairs,
                                             const int* __restrict__ tile_nodes,
                                             const float* __restrict__ sett2_w, const float* __restrict__ sett2_b,
                                             const float* __restrict__ city2_w, const float* __restrict__ city2_b,
                                             const float* __restrict__ road2_w, const float* __restrict__ road2_b,
                                             const float* __restrict__ rob2_w, const float* __restrict__ rob2_b,
                                             float* __restrict__ out, int B) {
    extern __shared__ char smem[];
    const uint32_t sbase = smem_u32(smem);
    const int tid = threadIdx.x, wid = tid >> 5, lane = tid & 31;

    float* xs      = (float*)(smem + SM_XP);   // rows x 52
    float* P_s     = (float*)(smem + SM_XP);   // rows x 97 (overlay)
    float* tproj_s = (float*)(smem + SM_TPROJ);
    float* w2_s    = (float*)(smem + SM_W2);
    float* rob2_s  = (float*)(smem + SM_ROB2);
    float* b2_s    = (float*)(smem + SM_B2);
    float* lnw     = (float*)(smem + SM_LNW);
    float* lnb     = (float*)(smem + SM_LNB);
    float* mu_s    = (float*)(smem + SM_MU);
    float* is_s    = (float*)(smem + SM_IS);
    int*   rp_s    = (int*)(smem + SM_RP);
    int*   ti_s    = (int*)(smem + SM_TI);

    for (int i = tid; i < 160 * 48; i += 256) {
        int n = i / 48, k = i % 48;
        *(__half*)(smem + SM_WH + (n * 56 + k) * 2) = d_Wh[i];
        *(__half*)(smem + SM_WL + (n * 56 + k) * 2) = d_Wl[i];
    }
    if (tid < 48) { lnw[tid] = ln_n_w[tid]; lnb[tid] = ln_n_b[tid]; }
    if (tid < 32) { w2_s[tid] = sett2_w[tid]; w2_s[32 + tid] = city2_w[tid]; w2_s[64 + tid] = road2_w[tid]; }
    if (tid < 160) rob2_s[tid] = rob2_w[tid];
    if (tid == 0) { b2_s[0] = sett2_b[0]; b2_s[1] = city2_b[0]; b2_s[2] = road2_b[0]; }
    if (tid < 5) b2_s[3 + tid] = rob2_b[tid];
    if (tid < 144) rp_s[tid] = road_pairs[tid];
    if (tid < 114) ti_s[tid] = tile_nodes[tid];

    const int g = lane >> 2;
    const int k0 = (lane & 3) * 2;
    const int mrow = (wid & 3) * 32;
    const int nbase = (wid >> 2) * 10;

    int rown[4]; const float* tpp[4];
    #pragma unroll
    for (int s = 0; s < 4; s++) {
        rown[s] = mrow + 16 * (s >> 1) + 8 * (s & 1) + g;
        tpp[s] = tproj_s + ((rown[s] >= 54) ? 128 : 0);
    }

    const long npairs = ((long)B + 1) / 2;
    const size_t tot4 = (size_t)B * 648;     // node_emb float4 count
    const size_t totp4 = (size_t)B * 32;     // tproj float4 count
    const float4* ne4 = (const float4*)node_emb;
    const float4* tp4 = (const float4*)d_tproj;

    for (long pair = blockIdx.x; pair < npairs; pair += gridDim.x) {
        // ---- stage via cp.async: node rows into xs (stride 52), tproj ----
        {
            size_t base4 = (size_t)pair * 1296;
            #pragma unroll
            for (int q = 0; q < 6; q++) {
                int il = tid + q * 256;
                if (il < 1296 && base4 + il < tot4) {
                    int row = il / 12, c = il % 12;
                    cp16(sbase + SM_XP + (uint32_t)((row * 52 + 4 * c) * 4), ne4 + base4 + il);
                }
            }
            if (tid < 64) {
                size_t t4 = (size_t)pair * 64 + tid;
                if (t4 < totp4) cp16(sbase + SM_TPROJ + tid * 16, tp4 + t4);
            }
            asm volatile("cp.async.commit_group;" ::: "memory");
            asm volatile("cp.async.wait_group 0;" ::: "memory");
        }
        __syncthreads();

        const int nrows = (int)((long)B * 54 - pair * 108 >= 108 ? 108 : (long)B * 54 - pair * 108);

        // ---- LN phase A: thread-per-row sums ----
        if (tid < nrows) {
            const float4* xr = (const float4*)(xs + tid * 52);
            float s = 0.f, q = 0.f;
            #pragma unroll
            for (int j = 0; j < 12; j++) {
                float4 v = xr[j];
                s += v.x + v.y + v.z + v.w;
                q += v.x * v.x + v.y * v.y + v.z * v.z + v.w * v.w;
            }
            float mu = s * (1.f / 48.f);
            mu_s[tid] = mu;
            is_s[tid] = rsqrtf(q * (1.f / 48.f) - mu * mu + 1e-5f);
        }
        __syncthreads();

        // ---- LN phase B: vectorized split into AH/AL ----
        for (int i = tid; i < 2592; i += 256) {
            int r = i / 24, c2 = (i % 24) * 2;
            if (r < nrows) {
                float2 v = *(const float2*)(xs + r * 52 + c2);
                float mu = mu_s[r], is = is_s[r];
                float v0 = (v.x - mu) * is * lnw[c2] + lnb[c2];
                float v1 = (v.y - mu) * is * lnw[c2 + 1] + lnb[c2 + 1];
                __half2 h = __floats2half2_rn(v0, v1);
                __half2 l = __floats2half2_rn(v0 - __low2float(h), v1 - __high2float(h));
                *(__half2*)(smem + SM_AH + (r * 56 + c2) * 2) = h;
                *(__half2*)(smem + SM_AL + (r * 56 + c2) * 2) = l;
            }
        }
        __syncthreads();

        // ---- A fragments ----
        uint32_t afh[2][3][4], afl[2][3][4];
        #pragma unroll
        for (int t = 0; t < 2; t++) {
            #pragma unroll
            for (int ks = 0; ks < 3; ks++) {
                const char* ba = smem + SM_AH + ((mrow + 16 * t + g) * 56 + k0 + 16 * ks) * 2;
                afh[t][ks][0] = *(const uint32_t*)(ba);
                afh[t][ks][1] = *(const uint32_t*)(ba + 896);
                afh[t][ks][2] = *(const uint32_t*)(ba + 16);
                afh[t][ks][3] = *(const uint32_t*)(ba + 896 + 16);
                const char* bl = ba + (SM_AL - SM_AH);
                afl[t][ks][0] = *(const uint32_t*)(bl);
                afl[t][ks][1] = *(const uint32_t*)(bl + 896);
                afl[t][ks][2] = *(const uint32_t*)(bl + 16);
                afl[t][ks][3] = *(const uint32_t*)(bl + 896 + 16);
            }
        }

        float sacc[4] = {0.f, 0.f, 0.f, 0.f}, cacc[4] = {0.f, 0.f, 0.f, 0.f};

        #pragma unroll
        for (int ni = 0; ni < 10; ni++) {
            const int nt = nbase + ni;
            float acc[2][4] = {{0.f, 0.f, 0.f, 0.f}, {0.f, 0.f, 0.f, 0.f}};
            const char* wb = smem + SM_WH + ((nt * 8 + g) * 56 + k0) * 2;
            #pragma unroll
            for (int ks = 0; ks < 3; ks++) {
                uint32_t bh0 = *(const uint32_t*)(wb + 32 * ks);
                uint32_t bh1 = *(const uint32_t*)(wb + 32 * ks + 16);
                uint32_t bl0 = *(const uint32_t*)(wb + 32 * ks + (SM_WL - SM_WH));
                uint32_t bl1 = *(const uint32_t*)(wb + 32 * ks + 16 + (SM_WL - SM_WH));
                #pragma unroll
                for (int t = 0; t < 2; t++) {
                    mma16816(acc[t], afh[t][ks], bh0, bh1);
                    mma16816(acc[t], afh[t][ks], bl0, bl1);
                    mma16816(acc[t], afl[t][ks], bh0, bh1);
                }
            }
            const int col = nt * 8 + k0;
            if (nt < 8) {
                float w2a = w2_s[col], w2b = w2_s[col + 1];
                float* dst = (nt < 4) ? sacc : cacc;
                #pragma unroll
                for (int s = 0; s < 4; s++) {
                    float v0 = acc[s >> 1][2 * (s & 1)];
                    float v1 = acc[s >> 1][2 * (s & 1) + 1];
                    dst[s] += mishf(v0 + tpp[s][col]) * w2a + mishf(v1 + tpp[s][col + 1]) * w2b;
                }
            } else {
                #pragma unroll
                for (int s = 0; s < 4; s++) {
                    int r = rown[s];
                    if (r < 108) {
                        float* pr = P_s + r * 97 + (col - 64);
                        pr[0] = acc[s >> 1][2 * (s & 1)];
                        pr[1] = acc[s >> 1][2 * (s & 1) + 1];
                    }
                }
            }
        }

        // sett/city finalize (warps 0-3 cover cols 0:64)
        if (wid < 4) {
            #pragma unroll
            for (int s = 0; s < 4; s++) {
                sacc[s] += __shfl_xor_sync(0xffffffffu, sacc[s], 1);
                sacc[s] += __shfl_xor_sync(0xffffffffu, sacc[s], 2);
                cacc[s] += __shfl_xor_sync(0xffffffffu, cacc[s], 1);
                cacc[s] += __shfl_xor_sync(0xffffffffu, cacc[s], 2);
            }
            if ((lane & 3) == 0) {
                #pragma unroll
                for (int s = 0; s < 4; s++) {
                    int r = rown[s];
                    if (r < nrows) {
                        int bl = (r >= 54) ? 1 : 0;
                        int n = r - 54 * bl;
                        size_t ob = ((size_t)(pair * 2 + bl)) * 397;
                        out[ob + 5 + n]  = sacc[s] + b2_s[0];
                        out[ob + 59 + n] = cacc[s] + b2_s[1];
                    }
                }
            }
        }
        __syncthreads();

        const int nb = (nrows > 54) ? 2 : 1;
        for (int t = wid; t < nb * 72; t += 8) {
            int bl = t / 72, e = t - 72 * bl;
            int sN = rp_s[2 * e], dN = rp_s[2 * e + 1];
            float hv = tproj_s[bl * 128 + 64 + lane]
                     + P_s[(bl * 54 + sN) * 97 + lane]
                     + P_s[(bl * 54 + dN) * 97 + 32 + lane];
            float red = warp_sum(mishf(hv) * w2_s[64 + lane]);
            if (lane == 0) out[((size_t)(pair * 2 + bl)) * 397 + 113 + e] = red + b2_s[2];
        }
        for (int t = wid; t < nb * 19; t += 8) {
            int bl = t / 19, tt = t - 19 * bl;
            float a = 0.f;
            #pragma unroll
            for (int i = 0; i < 6; i++)
                a += P_s[(bl * 54 + ti_s[tt * 6 + i]) * 97 + 64 + lane];
            float m = mishf(tproj_s[bl * 128 + 96 + lane] + a * (1.f / 6.f));
            #pragma unroll
            for (int o = 0; o < 5; o++) {
                float red = warp_sum(m * rob2_s[o * 32 + lane]);
                if (lane == 0)
                    out[((size_t)(pair * 2 + bl)) * 397 + 185 + tt * 5 + o] = red + b2_s[3 + o];
            }
        }
        __syncthreads();   // protect xs/P_s overlay before next staging
    }
}

// ------------------------------ K3 ------------------------------
__global__ __launch_bounds__(128) void k3(const float* __restrict__ gfc2_w,
                                          const float* __restrict__ gfc2_b,
                                          float* __restrict__ out, int B) {
    __shared__ float Wg[80 * 122];
    __shared__ float bs[122];
    __shared__ float m_s[80];
    __shared__ float sc[80], sh[80];
    int tid = threadIdx.x;
    for (int i = tid; i < 80 * 122; i += 128) {
        int k = i / 122, t = i % 122;
        int r = (t < 5) ? t : (275 + t);
        Wg[i] = gfc2_w[r * 80 + k];
    }
    if (tid < 122) { int r = (tid < 5) ? tid : (275 + tid); bs[tid] = gfc2_b[r]; }
    if (tid < 80) { sc[tid] = d_bnscale[tid]; sh[tid] = d_bnshift[tid]; }
    __syncthreads();
    for (int b = blockIdx.x; b < B; b += gridDim.x) {
        if (tid < 80) m_s[tid] = mishf(d_h[(size_t)b * 80 + tid] * sc[tid] + sh[tid]);
        __syncthreads();
        if (tid < 122) {
            float a = bs[tid];
            for (int k = 0; k < 80; k++) a += m_s[k] * Wg[k * 122 + tid];
            int col = (tid < 5) ? tid : (275 + tid);
            out[(size_t)b * 397 + col] = a;
        }
        __syncthreads();
    }
}

// ------------------------------ launch ------------------------------
extern "C" void kernel_launch(void* const* d_in, const int* in_sizes, int n_in,
                              void* d_out, int out_size) {
    const float* trunk      = (const float*)d_in[0];
    const float* node_emb   = (const float*)d_in[1];
    const int*   road_pairs = (const int*)d_in[2];
    const int*   tile_nodes = (const int*)d_in[3];
    const float* ln_t_w = (const float*)d_in[4];
    const float* ln_t_b = (const float*)d_in[5];
    const float* ln_n_w = (const float*)d_in[6];
    const float* ln_n_b = (const float*)d_in[7];
    const float* gfc1_w = (const float*)d_in[8];
    const float* gfc1_b = (const float*)d_in[9];
    const float* bn_w   = (const float*)d_in[10];
    const float* bn_b   = (const float*)d_in[11];
    const float* gfc2_w = (const float*)d_in[12];
    const float* gfc2_b = (const float*)d_in[13];
    const float* sett1_w = (const float*)d_in[14];
    const float* sett1_b = (const float*)d_in[15];
    const float* sett2_w = (const float*)d_in[16];
    const float* sett2_b = (const float*)d_in[17];
    const float* city1_w = (const float*)d_in[18];
    const float* city1_b = (const float*)d_in[19];
    const float* city2_w = (const float*)d_in[20];
    const float* city2_b = (const float*)d_in[21];
    const float* road1_w = (const float*)d_in[22];
    const float* road1_b = (const float*)d_in[23];
    const float* road2_w = (const float*)d_in[24];
    const float* road2_b = (const float*)d_in[25];
    const float* rob1_w = (const float*)d_in[26];
    const float* rob1_b = (const float*)d_in[27];
    const float* rob2_w = (const float*)d_in[28];
    const float* rob2_b = (const float*)d_in[29];

    int B = in_sizes[0] / 80;
    if (B > BMAX) B = BMAX;
    float* out = (float*)d_out;

    const int K1_SMEM = (16640 + 208 + 80 + 80 + 640 + 1280) * 4;

    cudaFuncSetAttribute(k1, cudaFuncAttributeMaxDynamicSharedMemorySize, K1_SMEM);
    cudaFuncSetAttribute(k2, cudaFuncAttributeMaxDynamicSharedMemorySize, SM_TOTAL);

    k_prep<<<(80 * 208 + 255) / 256, 256>>>(sett1_w, city1_w, road1_w, rob1_w, gfc1_w,
                                            sett1_b, city1_b, road1_b, rob1_b, gfc1_b);
    k1<<<K1_GRID, 256, K1_SMEM>>>(trunk, ln_t_w, ln_t_b, B);
    k_bn<<<1, 80>>>(bn_w, bn_b, B);
    k2<<<K2_GRID, 256, SM_TOTAL>>>(node_emb, ln_n_w, ln_n_b, road_pairs, tile_nodes,
                                   sett2_w, sett2_b, city2_w, city2_b,
                                   road2_w, road2_b, rob2_w, rob2_b, out, B);
    k3<<<K3_GRID, 128>>>(gfc2_w, gfc2_b, out, B);
}